// round 6
// baseline (speedup 1.0000x reference)
#include <cuda_runtime.h>
#include <cuda_fp16.h>
#include <cstdint>

// Problem constants
#define TPc   4
#define WSZ   16
#define B_    8
#define F_    256
#define K_    64
#define EDv   256
#define NWIN  2048
#define WTYPES 256

// Shared memory layout (byte offsets)
#define OFF_WSM 33792     // buf: 64 rows x 528B (264 halfs)
#define WCH_B   20480     // one Wp chunk buffer: 256 rows x 80B
#define OFF_AS  74752     // As: 64 rows x 144B
#define OFF_GS  83968
#define OFF_BS  84992
#define OFF_BPS 86016
#define OFF_MU  87040
#define OFF_RS  87296
#define OFF_GR  87552
#define SMEM_REQ 87808

#define BUF_S32 132       // buf row stride in b32 (264 halfs); 528B = 33x16B (odd)
#define BUF_SB  528
#define W_SB    80        // Wp chunk row stride: 32 halfs + 16B pad; 80 = 5x16B (odd)
#define A_SB    144       // As row stride: 64 halfs + 16B pad; 144 = 9x16B (odd)

// Precomputed fp16 operands (device globals: no allocation)
__device__ __half g_Wh[EDv * EDv];            // Wp as fp16, row-major [o][k]
__device__ __half g_Ah[WTYPES * 64 * 64];     // A = deg@eb as fp16

// ---------------------------------------------------------------------------
// Prep kernel 1: Wp -> fp16
// ---------------------------------------------------------------------------
__global__ __launch_bounds__(256) void convert_Wp_kernel(const float* __restrict__ Wp)
{
    int i = blockIdx.x * 256 + threadIdx.x;
    g_Wh[i] = __float2half_rn(Wp[i]);
}

// ---------------------------------------------------------------------------
// Prep kernel 2: A[w] = deg[w] @ eb[w] (fp32 FFMA), stored as fp16
// ---------------------------------------------------------------------------
__global__ __launch_bounds__(256) void compute_A_kernel(
    const float* __restrict__ deg, const float* __restrict__ eb)
{
    __shared__ float Ds[64][64];
    __shared__ float Es[64][68];
    int w = blockIdx.x, tid = threadIdx.x;
    const float* D = deg + (size_t)w * 4096;
    const float* E = eb  + (size_t)w * 4096;
    for (int idx = tid; idx < 4096; idx += 256) {
        Ds[idx >> 6][idx & 63] = D[idx];
        Es[idx >> 6][idx & 63] = E[idx];
    }
    __syncthreads();
    int p  = tid >> 2;
    int q0 = (tid & 3) * 16;
    float acc[16];
#pragma unroll
    for (int j = 0; j < 16; j++) acc[j] = 0.f;
    for (int k = 0; k < 64; k++) {
        float a = Ds[p][k];
#pragma unroll
        for (int j = 0; j < 16; j++) acc[j] = fmaf(a, Es[k][q0 + j], acc[j]);
    }
    __half* Aout = g_Ah + (size_t)w * 4096 + p * 64 + q0;
#pragma unroll
    for (int j = 0; j < 16; j++) Aout[j] = __float2half_rn(acc[j]);
}

// ---------------------------------------------------------------------------
// mma / ldmatrix / cp.async helpers
// ---------------------------------------------------------------------------
__device__ __forceinline__ uint32_t smem_u32(const void* p) {
    uint32_t a;
    asm("{ .reg .u64 t; cvta.to.shared.u64 t, %1; cvt.u32.u64 %0, t; }" : "=r"(a) : "l"(p));
    return a;
}

#define LDSM4(r0, r1, r2, r3, addr) \
    asm volatile("ldmatrix.sync.aligned.m8n8.x4.shared.b16 {%0,%1,%2,%3}, [%4];" \
                 : "=r"(r0), "=r"(r1), "=r"(r2), "=r"(r3) : "r"(addr))
#define LDSM4T(r0, r1, r2, r3, addr) \
    asm volatile("ldmatrix.sync.aligned.m8n8.x4.trans.shared.b16 {%0,%1,%2,%3}, [%4];" \
                 : "=r"(r0), "=r"(r1), "=r"(r2), "=r"(r3) : "r"(addr))

__device__ __forceinline__ void hmma(float c[4], const uint32_t a[4],
                                     uint32_t b0, uint32_t b1) {
    asm volatile(
        "mma.sync.aligned.m16n8k16.row.col.f32.f16.f16.f32 "
        "{%0,%1,%2,%3}, {%4,%5,%6,%7}, {%8,%9}, {%0,%1,%2,%3};"
        : "+f"(c[0]), "+f"(c[1]), "+f"(c[2]), "+f"(c[3])
        : "r"(a[0]), "r"(a[1]), "r"(a[2]), "r"(a[3]), "r"(b0), "r"(b1));
}

#define CP16(dst, src) \
    asm volatile("cp.async.cg.shared.global [%0], [%1], 16;" :: "r"(dst), "l"(src))
#define CP_COMMIT() asm volatile("cp.async.commit_group;" ::: "memory")
#define CP_WAIT1()  asm volatile("cp.async.wait_group 1;" ::: "memory")
#define CP_WAIT0()  asm volatile("cp.async.wait_group 0;" ::: "memory")

// ---------------------------------------------------------------------------
// Fused kernel: one 256-thread CTA per window (2 CTAs/SM).
//   cp.async prologue (Wp0, As, Wp1) -> LN (2-pass gmem) -> buf(half)
//   -> GEMM1 (8x32k chunks, double-buffered cp.async Wp) -> y in buf
//   -> GEMM2 (A_w @ y) -> direct float2 scatter to gmem (window_reverse)
// ---------------------------------------------------------------------------
__global__ __launch_bounds__(256, 2) void fused_fp16(
    const float* __restrict__ x, const float* __restrict__ gamma,
    const float* __restrict__ beta, const float* __restrict__ bp_,
    float* __restrict__ out)
{
    extern __shared__ char smc[];
    __half2* buf2 = (__half2*)smc;
    float* gs   = (float*)(smc + OFF_GS);
    float* bs   = (float*)(smc + OFF_BS);
    float* bps  = (float*)(smc + OFF_BPS);
    float* mu_s = (float*)(smc + OFF_MU);
    float* rs_s = (float*)(smc + OFF_RS);
    int*   grows= (int*)  (smc + OFF_GR);

    const uint32_t buf_u = smem_u32(smc);
    const uint32_t wsm_u = buf_u + OFF_WSM;
    const uint32_t as_u  = buf_u + OFF_AS;

    const int tid  = threadIdx.x;
    const int lane = tid & 31;
    const int wid  = tid >> 5;

    const int n   = blockIdx.x;
    const int b   = n >> 8;
    const int w   = n & 255;
    const int fi  = w >> 2;
    const int nwi = w & 3;

    // ---- cp.async prologue: Wp chunk0 + A tile (group 0), Wp chunk1 (group 1)
    const char* whb = (const char*)g_Wh;
    const char* ahb = (const char*)(g_Ah + (size_t)w * 4096);
    {
        // Wp chunk 0 -> buffer 0
#pragma unroll
        for (int i = 0; i < 4; i++) {
            int idx = tid + i * 256;           // 1024 x 16B
            int chan = idx >> 2, seg = idx & 3;
            CP16(wsm_u + (uint32_t)(chan * W_SB + seg * 16),
                 whb + (size_t)chan * 512 + seg * 16);
        }
        // A tile
#pragma unroll
        for (int i = 0; i < 2; i++) {
            int idx = tid + i * 256;           // 512 x 16B
            int row = idx >> 3, seg = idx & 7;
            CP16(as_u + (uint32_t)(row * A_SB + seg * 16),
                 ahb + (size_t)row * 128 + seg * 16);
        }
        CP_COMMIT();
        // Wp chunk 1 -> buffer 1
#pragma unroll
        for (int i = 0; i < 4; i++) {
            int idx = tid + i * 256;
            int chan = idx >> 2, seg = idx & 3;
            CP16(wsm_u + (uint32_t)(WCH_B + chan * W_SB + seg * 16),
                 whb + (size_t)chan * 512 + 64 + seg * 16);
        }
        CP_COMMIT();
    }

    gs[tid]  = gamma[tid];
    bs[tid]  = beta[tid];
    bps[tid] = bp_[tid];

    // ---- LN pass 1: per-token mean/rstd from gmem fp32 (4 threads/token) ----
    {
        int t = tid >> 2, q = tid & 3;
        int tp = t >> 4, wi2 = t & 15;
        int grow = (b * F_ + fi * TPc + tp) * K_ + nwi * WSZ + wi2;
        if (q == 0) grows[t] = grow;
        const float4* p = (const float4*)(x + (size_t)grow * EDv + q * 64);
        float s = 0.f, ss = 0.f;
#pragma unroll
        for (int i = 0; i < 16; i++) {
            float4 v = p[i];
            s += v.x + v.y + v.z + v.w;
            ss = fmaf(v.x, v.x, ss); ss = fmaf(v.y, v.y, ss);
            ss = fmaf(v.z, v.z, ss); ss = fmaf(v.w, v.w, ss);
        }
        s  += __shfl_xor_sync(0xffffffffu, s, 1);
        ss += __shfl_xor_sync(0xffffffffu, ss, 1);
        s  += __shfl_xor_sync(0xffffffffu, s, 2);
        ss += __shfl_xor_sync(0xffffffffu, ss, 2);
        if (q == 0) {
            float mu  = s * (1.f / 256.f);
            float var = ss * (1.f / 256.f) - mu * mu;
            mu_s[t] = mu;
            rs_s[t] = rsqrtf(var + 1e-5f);
        }
    }
    __syncthreads();

    // ---- LN pass 2: normalize (gmem reload, L2-hot) -> half2 into buf ----
    {
        float g0[4], g1[4], e0[4], e1[4];
#pragma unroll
        for (int j = 0; j < 4; j++) {
            int c = 64 * j + 2 * lane;
            g0[j] = gs[c]; g1[j] = gs[c + 1];
            e0[j] = bs[c]; e1[j] = bs[c + 1];
        }
#pragma unroll
        for (int t8 = 0; t8 < 8; t8++) {
            int t = wid * 8 + t8;
            float mu = mu_s[t], rstd = rs_s[t];
            const float* xr = x + (size_t)grows[t] * EDv;
#pragma unroll
            for (int j = 0; j < 4; j++) {
                float2 v = *(const float2*)(xr + 64 * j + 2 * lane);
                buf2[t * BUF_S32 + 32 * j + lane] = __floats2half2_rn(
                    (v.x - mu) * rstd * g0[j] + e0[j],
                    (v.y - mu) * rstd * g1[j] + e1[j]);
            }
        }
    }

    const int n0 = wid * 32;
    const int r4 = lane >> 2, c4 = lane & 3;

    // ldmatrix lane->address parameters
    const int arow  = (lane & 7) + ((lane >> 3) & 1) * 8;  // A row within 16
    const int khi   = (lane >> 4) * 8;                     // +8 halfs (hi-k lanes)
    const int bnrow = ((lane >> 4) & 1) * 8 + (lane & 7);  // B n-row within 16
    const int bkhi  = ((lane >> 3) & 1) * 8;               // B k offset
    const int tkrow = ((lane >> 3) & 1) * 8 + (lane & 7);  // trans: k row within 16
    const int tnhi  = (lane >> 4) * 8;                     // trans: n +8

    float acc[4][4][4];
#pragma unroll
    for (int mt = 0; mt < 4; mt++)
#pragma unroll
        for (int nt = 0; nt < 4; nt++)
#pragma unroll
            for (int r = 0; r < 4; r++) acc[mt][nt][r] = 0.f;

    // ---- GEMM1: y(64x256) = xn @ Wp^T; 8 chunks of k=32, double-buffered ----
    for (int kc = 0; kc < 8; kc++) {
        const int bsel = kc & 1;
        if (kc < 7) { CP_WAIT1(); } else { CP_WAIT0(); }
        __syncthreads();   // chunk kc resident for all threads (also covers LN/buf on kc==0)

#pragma unroll
        for (int ks = 0; ks < 2; ks++) {
            uint32_t a[4][4];
            uint32_t abase = buf_u + (uint32_t)arow * BUF_SB +
                             (uint32_t)(kc * 32 + ks * 16 + khi) * 2;
#pragma unroll
            for (int mt = 0; mt < 4; mt++)
                LDSM4(a[mt][0], a[mt][1], a[mt][2], a[mt][3],
                      abase + (uint32_t)(mt * 16) * BUF_SB);
            uint32_t bb[4][2];
#pragma unroll
            for (int ntp = 0; ntp < 2; ntp++) {
                uint32_t baddr = wsm_u + (uint32_t)bsel * WCH_B +
                                 (uint32_t)(n0 + ntp * 16 + bnrow) * W_SB +
                                 (uint32_t)(ks * 16 + bkhi) * 2;
                LDSM4(bb[2 * ntp][0], bb[2 * ntp][1],
                      bb[2 * ntp + 1][0], bb[2 * ntp + 1][1], baddr);
            }
#pragma unroll
            for (int mt = 0; mt < 4; mt++)
#pragma unroll
                for (int nt = 0; nt < 4; nt++)
                    hmma(acc[mt][nt], a[mt], bb[nt][0], bb[nt][1]);
        }
        __syncthreads();   // all warps done with buffer bsel of chunk kc

        if (kc < 6) {      // stage chunk kc+2 into buffer bsel
            int kn = kc + 2;
#pragma unroll
            for (int i = 0; i < 4; i++) {
                int idx = tid + i * 256;
                int chan = idx >> 2, seg = idx & 3;
                CP16(wsm_u + (uint32_t)(bsel * WCH_B + chan * W_SB + seg * 16),
                     whb + (size_t)chan * 512 + kn * 64 + seg * 16);
            }
            CP_COMMIT();
        }
    }

    // ---- epilogue1: y = acc + bias -> half2 into buf [tok][chan] ----
    {
        float p0[4], p1[4];
#pragma unroll
        for (int nt = 0; nt < 4; nt++) {
            int c = n0 + nt * 8 + 2 * c4;
            p0[nt] = bps[c]; p1[nt] = bps[c + 1];
        }
#pragma unroll
        for (int mt = 0; mt < 4; mt++)
#pragma unroll
            for (int nt = 0; nt < 4; nt++) {
                int row = mt * 16 + r4;
                int cc = (n0 + nt * 8 + 2 * c4) >> 1;
                buf2[row * BUF_S32 + cc] =
                    __floats2half2_rn(acc[mt][nt][0] + p0[nt], acc[mt][nt][1] + p1[nt]);
                buf2[(row + 8) * BUF_S32 + cc] =
                    __floats2half2_rn(acc[mt][nt][2] + p0[nt], acc[mt][nt][3] + p1[nt]);
            }
    }
    __syncthreads();

    // ---- GEMM2: z(64x256) = A_w(64x64) @ y ----
#pragma unroll
    for (int mt = 0; mt < 4; mt++)
#pragma unroll
        for (int nt = 0; nt < 4; nt++)
#pragma unroll
            for (int r = 0; r < 4; r++) acc[mt][nt][r] = 0.f;

#pragma unroll
    for (int ks = 0; ks < 4; ks++) {
        uint32_t a[4][4];
        uint32_t abase = as_u + (uint32_t)arow * A_SB + (uint32_t)(ks * 16 + khi) * 2;
#pragma unroll
        for (int mt = 0; mt < 4; mt++)
            LDSM4(a[mt][0], a[mt][1], a[mt][2], a[mt][3],
                  abase + (uint32_t)(mt * 16) * A_SB);
        uint32_t bb[4][2];
#pragma unroll
        for (int ntp = 0; ntp < 2; ntp++) {
            uint32_t baddr = buf_u + (uint32_t)(ks * 16 + tkrow) * BUF_SB +
                             (uint32_t)(n0 + ntp * 16 + tnhi) * 2;
            LDSM4T(bb[2 * ntp][0], bb[2 * ntp][1],
                   bb[2 * ntp + 1][0], bb[2 * ntp + 1][1], baddr);
        }
#pragma unroll
        for (int mt = 0; mt < 4; mt++)
#pragma unroll
            for (int nt = 0; nt < 4; nt++)
                hmma(acc[mt][nt], a[mt], bb[nt][0], bb[nt][1]);
    }

    // ---- epilogue2: direct float2 scatter to gmem (window_reverse) ----
#pragma unroll
    for (int mt = 0; mt < 4; mt++) {
        int t0 = mt * 16 + r4;
        float* o0 = out + (size_t)grows[t0] * EDv;
        float* o1 = out + (size_t)grows[t0 + 8] * EDv;
#pragma unroll
        for (int nt = 0; nt < 4; nt++) {
            int col = n0 + nt * 8 + 2 * c4;
            *(float2*)(o0 + col) = make_float2(acc[mt][nt][0], acc[mt][nt][1]);
            *(float2*)(o1 + col) = make_float2(acc[mt][nt][2], acc[mt][nt][3]);
        }
    }
}

// ---------------------------------------------------------------------------
// Launch
// ---------------------------------------------------------------------------
extern "C" void kernel_launch(void* const* d_in, const int* in_sizes, int n_in,
                              void* d_out, int out_size)
{
    const float* x     = (const float*)d_in[0];
    const float* gamma = (const float*)d_in[1];
    const float* beta  = (const float*)d_in[2];
    const float* Wp    = (const float*)d_in[3];
    const float* bp    = (const float*)d_in[4];
    const float* eb    = (const float*)d_in[5];
    const float* deg   = (const float*)d_in[6];
    float* out = (float*)d_out;

    convert_Wp_kernel<<<EDv * EDv / 256, 256>>>(Wp);
    compute_A_kernel<<<WTYPES, 256>>>(deg, eb);

    cudaFuncSetAttribute(fused_fp16,
                         cudaFuncAttributeMaxDynamicSharedMemorySize, SMEM_REQ);
    fused_fp16<<<NWIN, 256, SMEM_REQ>>>(x, gamma, beta, bp, out);
}

// round 7
// speedup vs baseline: 1.4019x; 1.4019x over previous
#include <cuda_runtime.h>
#include <cuda_fp16.h>
#include <cstdint>

// Problem constants
#define TPc   4
#define WSZ   16
#define B_    8
#define F_    256
#define K_    64
#define EDv   256
#define NWIN  2048
#define WTYPES 256

// Shared memory layout (byte offsets)
#define OFF_WSM 33792     // buf: 64 rows x 528B (264 halfs)
#define OFF_AS  70656     // Wsm: 256 rows x 144B
#define OFF_GS  79872     // As:  64 rows x 144B
#define OFF_BS  80896
#define OFF_BPS 81920
#define OFF_MU  82944
#define OFF_RS  83200
#define OFF_GR  83456
#define SMEM_REQ 83712

#define BUF_S32 132       // buf row stride in b32 (264 halfs); 528B = 33x16B (odd)
#define BUF_SB  528
#define W_SB    144       // Wsm/As row stride: 64 halfs + 16B pad; 144 = 9x16B (odd)

// Precomputed fp16 operands (device globals: no allocation)
__device__ __half g_Wh[EDv * EDv];            // Wp as fp16, row-major [o][k]
__device__ __half g_Ah[WTYPES * 64 * 64];     // A = deg@eb as fp16

// ---------------------------------------------------------------------------
// Prep kernel 1: Wp -> fp16
// ---------------------------------------------------------------------------
__global__ __launch_bounds__(256) void convert_Wp_kernel(const float* __restrict__ Wp)
{
    int i = blockIdx.x * 256 + threadIdx.x;
    g_Wh[i] = __float2half_rn(Wp[i]);
}

// ---------------------------------------------------------------------------
// Prep kernel 2: A[w] = deg[w] @ eb[w] (fp32 FFMA), stored as fp16
// ---------------------------------------------------------------------------
__global__ __launch_bounds__(256) void compute_A_kernel(
    const float* __restrict__ deg, const float* __restrict__ eb)
{
    __shared__ float Ds[64][64];
    __shared__ float Es[64][68];
    int w = blockIdx.x, tid = threadIdx.x;
    const float* D = deg + (size_t)w * 4096;
    const float* E = eb  + (size_t)w * 4096;
    for (int idx = tid; idx < 4096; idx += 256) {
        Ds[idx >> 6][idx & 63] = D[idx];
        Es[idx >> 6][idx & 63] = E[idx];
    }
    __syncthreads();
    int p  = tid >> 2;
    int q0 = (tid & 3) * 16;
    float acc[16];
#pragma unroll
    for (int j = 0; j < 16; j++) acc[j] = 0.f;
    for (int k = 0; k < 64; k++) {
        float a = Ds[p][k];
#pragma unroll
        for (int j = 0; j < 16; j++) acc[j] = fmaf(a, Es[k][q0 + j], acc[j]);
    }
    __half* Aout = g_Ah + (size_t)w * 4096 + p * 64 + q0;
#pragma unroll
    for (int j = 0; j < 16; j++) Aout[j] = __float2half_rn(acc[j]);
}

// ---------------------------------------------------------------------------
// mma / ldmatrix helpers
// ---------------------------------------------------------------------------
__device__ __forceinline__ uint32_t smem_u32(const void* p) {
    uint32_t a;
    asm("{ .reg .u64 t; cvta.to.shared.u64 t, %1; cvt.u32.u64 %0, t; }" : "=r"(a) : "l"(p));
    return a;
}

#define LDSM4(r0, r1, r2, r3, addr) \
    asm volatile("ldmatrix.sync.aligned.m8n8.x4.shared.b16 {%0,%1,%2,%3}, [%4];" \
                 : "=r"(r0), "=r"(r1), "=r"(r2), "=r"(r3) : "r"(addr))
#define LDSM4T(r0, r1, r2, r3, addr) \
    asm volatile("ldmatrix.sync.aligned.m8n8.x4.trans.shared.b16 {%0,%1,%2,%3}, [%4];" \
                 : "=r"(r0), "=r"(r1), "=r"(r2), "=r"(r3) : "r"(addr))

__device__ __forceinline__ void hmma(float c[4], const uint32_t a[4],
                                     uint32_t b0, uint32_t b1) {
    asm volatile(
        "mma.sync.aligned.m16n8k16.row.col.f32.f16.f16.f32 "
        "{%0,%1,%2,%3}, {%4,%5,%6,%7}, {%8,%9}, {%0,%1,%2,%3};"
        : "+f"(c[0]), "+f"(c[1]), "+f"(c[2]), "+f"(c[3])
        : "r"(a[0]), "r"(a[1]), "r"(a[2]), "r"(a[3]), "r"(b0), "r"(b1));
}

// ---------------------------------------------------------------------------
// Fused kernel: one 256-thread CTA per window (2 CTAs/SM).  R5 structure:
//   LN (2-pass gmem) -> buf(half);  A tile uint4-copied in prologue
//   GEMM1: 4 chunks of k=64, staged from g_Wh by uint4 copy (no cvt)
//   -> y in buf -> GEMM2 (A_w @ y) -> direct float2 scatter (window_reverse)
// ---------------------------------------------------------------------------
__global__ __launch_bounds__(256, 2) void fused_fp16(
    const float* __restrict__ x, const float* __restrict__ gamma,
    const float* __restrict__ beta, const float* __restrict__ bp_,
    float* __restrict__ out)
{
    extern __shared__ char smc[];
    __half2* buf2 = (__half2*)smc;
    float* gs   = (float*)(smc + OFF_GS);
    float* bs   = (float*)(smc + OFF_BS);
    float* bps  = (float*)(smc + OFF_BPS);
    float* mu_s = (float*)(smc + OFF_MU);
    float* rs_s = (float*)(smc + OFF_RS);
    int*   grows= (int*)  (smc + OFF_GR);

    const uint32_t buf_u = smem_u32(smc);
    const uint32_t wsm_u = buf_u + OFF_WSM;
    const uint32_t as_u  = buf_u + OFF_AS;

    const int tid  = threadIdx.x;
    const int lane = tid & 31;
    const int wid  = tid >> 5;

    const int n   = blockIdx.x;
    const int b   = n >> 8;
    const int w   = n & 255;
    const int fi  = w >> 2;
    const int nwi = w & 3;

    gs[tid]  = gamma[tid];
    bs[tid]  = beta[tid];
    bps[tid] = bp_[tid];

    // ---- prologue: stage A tile (64 x 128B) by uint4 copy, no cvt ----
    {
        const uint4* asrc = (const uint4*)(g_Ah + (size_t)w * 4096);
#pragma unroll
        for (int i = 0; i < 2; i++) {
            int idx = tid + i * 256;         // 512 x 16B
            int row = idx >> 3, seg = idx & 7;
            *(uint4*)(smc + OFF_AS + row * W_SB + seg * 16) = asrc[row * 8 + seg];
        }
    }

    // ---- LN pass 1: per-token mean/rstd from gmem fp32 (4 threads/token) ----
    {
        int t = tid >> 2, q = tid & 3;
        int tp = t >> 4, wi2 = t & 15;
        int grow = (b * F_ + fi * TPc + tp) * K_ + nwi * WSZ + wi2;
        if (q == 0) grows[t] = grow;
        const float4* p = (const float4*)(x + (size_t)grow * EDv + q * 64);
        float s = 0.f, ss = 0.f;
#pragma unroll
        for (int i = 0; i < 16; i++) {
            float4 v = p[i];
            s += v.x + v.y + v.z + v.w;
            ss = fmaf(v.x, v.x, ss); ss = fmaf(v.y, v.y, ss);
            ss = fmaf(v.z, v.z, ss); ss = fmaf(v.w, v.w, ss);
        }
        s  += __shfl_xor_sync(0xffffffffu, s, 1);
        ss += __shfl_xor_sync(0xffffffffu, ss, 1);
        s  += __shfl_xor_sync(0xffffffffu, s, 2);
        ss += __shfl_xor_sync(0xffffffffu, ss, 2);
        if (q == 0) {
            float mu  = s * (1.f / 256.f);
            float var = ss * (1.f / 256.f) - mu * mu;
            mu_s[t] = mu;
            rs_s[t] = rsqrtf(var + 1e-5f);
        }
    }
    __syncthreads();

    // ---- LN pass 2: normalize (gmem reload, L2-hot) -> half2 into buf ----
    {
        float g0[4], g1[4], e0[4], e1[4];
#pragma unroll
        for (int j = 0; j < 4; j++) {
            int c = 64 * j + 2 * lane;
            g0[j] = gs[c]; g1[j] = gs[c + 1];
            e0[j] = bs[c]; e1[j] = bs[c + 1];
        }
#pragma unroll
        for (int t8 = 0; t8 < 8; t8++) {
            int t = wid * 8 + t8;
            float mu = mu_s[t], rstd = rs_s[t];
            const float* xr = x + (size_t)grows[t] * EDv;
#pragma unroll
            for (int j = 0; j < 4; j++) {
                float2 v = *(const float2*)(xr + 64 * j + 2 * lane);
                buf2[t * BUF_S32 + 32 * j + lane] = __floats2half2_rn(
                    (v.x - mu) * rstd * g0[j] + e0[j],
                    (v.y - mu) * rstd * g1[j] + e1[j]);
            }
        }
    }

    const int n0 = wid * 32;
    const int r4 = lane >> 2, c4 = lane & 3;

    // ldmatrix lane->address parameters
    const int arow  = (lane & 7) + ((lane >> 3) & 1) * 8;  // A row within 16
    const int khi   = (lane >> 4) * 8;                     // +8 halfs (hi-k lanes)
    const int bnrow = ((lane >> 4) & 1) * 8 + (lane & 7);  // B n-row within 16
    const int bkhi  = ((lane >> 3) & 1) * 8;               // B k offset
    const int tkrow = ((lane >> 3) & 1) * 8 + (lane & 7);  // trans: k row within 16
    const int tnhi  = (lane >> 4) * 8;                     // trans: n +8

    float acc[4][4][4];
#pragma unroll
    for (int mt = 0; mt < 4; mt++)
#pragma unroll
        for (int nt = 0; nt < 4; nt++)
#pragma unroll
            for (int r = 0; r < 4; r++) acc[mt][nt][r] = 0.f;

    // ---- GEMM1: y(64x256) = xn @ Wp^T; 4 chunks of k=64 ----
    const uint4* wsrc = (const uint4*)g_Wh;   // [256 rows][32 uint4]
    for (int kc = 0; kc < 4; kc++) {
        if (kc) __syncthreads();
        // stage Wp chunk [256 o][64 k] fp16 by uint4 copy (8 per thread)
#pragma unroll
        for (int i = 0; i < 8; i++) {
            int idx = tid + i * 256;          // 2048 x 16B
            int chan = idx >> 3, seg = idx & 7;
            *(uint4*)(smc + OFF_WSM + chan * W_SB + seg * 16) =
                wsrc[chan * 32 + kc * 8 + seg];
        }
        __syncthreads();

#pragma unroll
        for (int ks = 0; ks < 4; ks++) {
            uint32_t a[4][4];
            uint32_t abase = buf_u + (uint32_t)arow * BUF_SB +
                             (uint32_t)(kc * 64 + ks * 16 + khi) * 2;
#pragma unroll
            for (int mt = 0; mt < 4; mt++)
                LDSM4(a[mt][0], a[mt][1], a[mt][2], a[mt][3],
                      abase + (uint32_t)(mt * 16) * BUF_SB);
            uint32_t bb[4][2];
#pragma unroll
            for (int ntp = 0; ntp < 2; ntp++) {
                uint32_t baddr = wsm_u + (uint32_t)(n0 + ntp * 16 + bnrow) * W_SB +
                                 (uint32_t)(ks * 16 + bkhi) * 2;
                LDSM4(bb[2 * ntp][0], bb[2 * ntp][1],
                      bb[2 * ntp + 1][0], bb[2 * ntp + 1][1], baddr);
            }
#pragma unroll
            for (int mt = 0; mt < 4; mt++)
#pragma unroll
                for (int nt = 0; nt < 4; nt++)
                    hmma(acc[mt][nt], a[mt], bb[nt][0], bb[nt][1]);
        }
    }
    __syncthreads();   // all warps done reading xn -> safe to overwrite buf

    // ---- epilogue1: y = acc + bias -> half2 into buf [tok][chan] ----
    {
        float p0[4], p1[4];
#pragma unroll
        for (int nt = 0; nt < 4; nt++) {
            int c = n0 + nt * 8 + 2 * c4;
            p0[nt] = bps[c]; p1[nt] = bps[c + 1];
        }
#pragma unroll
        for (int mt = 0; mt < 4; mt++)
#pragma unroll
            for (int nt = 0; nt < 4; nt++) {
                int row = mt * 16 + r4;
                int cc = (n0 + nt * 8 + 2 * c4) >> 1;
                buf2[row * BUF_S32 + cc] =
                    __floats2half2_rn(acc[mt][nt][0] + p0[nt], acc[mt][nt][1] + p1[nt]);
                buf2[(row + 8) * BUF_S32 + cc] =
                    __floats2half2_rn(acc[mt][nt][2] + p0[nt], acc[mt][nt][3] + p1[nt]);
            }
    }
    __syncthreads();

    // ---- GEMM2: z(64x256) = A_w(64x64) @ y ----
#pragma unroll
    for (int mt = 0; mt < 4; mt++)
#pragma unroll
        for (int nt = 0; nt < 4; nt++)
#pragma unroll
            for (int r = 0; r < 4; r++) acc[mt][nt][r] = 0.f;

#pragma unroll
    for (int ks = 0; ks < 4; ks++) {
        uint32_t a[4][4];
        uint32_t abase = as_u + (uint32_t)arow * W_SB + (uint32_t)(ks * 16 + khi) * 2;
#pragma unroll
        for (int mt = 0; mt < 4; mt++)
            LDSM4(a[mt][0], a[mt][1], a[mt][2], a[mt][3],
                  abase + (uint32_t)(mt * 16) * W_SB);
        uint32_t bb[4][2];
#pragma unroll
        for (int ntp = 0; ntp < 2; ntp++) {
            uint32_t baddr = buf_u + (uint32_t)(ks * 16 + tkrow) * BUF_SB +
                             (uint32_t)(n0 + ntp * 16 + tnhi) * 2;
            LDSM4T(bb[2 * ntp][0], bb[2 * ntp][1],
                   bb[2 * ntp + 1][0], bb[2 * ntp + 1][1], baddr);
        }
#pragma unroll
        for (int mt = 0; mt < 4; mt++)
#pragma unroll
            for (int nt = 0; nt < 4; nt++)
                hmma(acc[mt][nt], a[mt], bb[nt][0], bb[nt][1]);
    }

    // ---- epilogue2: direct float2 scatter to gmem (window_reverse) ----
#pragma unroll
    for (int mt = 0; mt < 4; mt++) {
        int t0 = mt * 16 + r4;
        float* o0 = out + (size_t)grows[t0] * EDv;
        float* o1 = out + (size_t)grows[t0 + 8] * EDv;
#pragma unroll
        for (int nt = 0; nt < 4; nt++) {
            int col = n0 + nt * 8 + 2 * c4;
            *(float2*)(o0 + col) = make_float2(acc[mt][nt][0], acc[mt][nt][1]);
            *(float2*)(o1 + col) = make_float2(acc[mt][nt][2], acc[mt][nt][3]);
        }
    }
}

// ---------------------------------------------------------------------------
// Launch
// ---------------------------------------------------------------------------
extern "C" void kernel_launch(void* const* d_in, const int* in_sizes, int n_in,
                              void* d_out, int out_size)
{
    const float* x     = (const float*)d_in[0];
    const float* gamma = (const float*)d_in[1];
    const float* beta  = (const float*)d_in[2];
    const float* Wp    = (const float*)d_in[3];
    const float* bp    = (const float*)d_in[4];
    const float* eb    = (const float*)d_in[5];
    const float* deg   = (const float*)d_in[6];
    float* out = (float*)d_out;

    convert_Wp_kernel<<<EDv * EDv / 256, 256>>>(Wp);
    compute_A_kernel<<<WTYPES, 256>>>(deg, eb);

    cudaFuncSetAttribute(fused_fp16,
                         cudaFuncAttributeMaxDynamicSharedMemorySize, SMEM_REQ);
    fused_fp16<<<NWIN, 256, SMEM_REQ>>>(x, gamma, beta, bp, out);
}